// round 16
// baseline (speedup 1.0000x reference)
#include <cuda_runtime.h>
#include <cuda_fp16.h>

// ---------------- problem constants ----------------
#define Bn 65536
#define Cn 128
#define Dn 32
#define Kn 10
#define NAUG 33
#define KPAD 576          // padded triangular size (18 chunks of 32)
#define KC 32
#define NCH 18
#define ROWS 128
#define THREADS 256
#define TILE 8192         // 128 x 32 fp16, 64B rows, SW64
#define GST 134           // gamma staging stride (floats)

#define SWZ64(o) ((o) ^ (((o) >> 3) & 0x30))

__device__ __align__(16) unsigned char g_Uh[2][NCH][TILE];
__device__ unsigned g_ijoff[KPAD];   // (4*i) | (4*j << 16) byte offsets into z row
__device__ int g_cls[Cn];

// ---------------- helpers ----------------
static __device__ __forceinline__ unsigned smem_u32(const void* p) {
    unsigned a;
    asm("{ .reg .u64 t; cvta.to.shared.u64 t, %1; cvt.u32.u64 %0, t; }"
        : "=r"(a) : "l"(p));
    return a;
}
static __device__ __forceinline__ void cp16(unsigned sdst, const void* gsrc) {
    asm volatile("cp.async.cg.shared.global [%0], [%1], 16;" :: "r"(sdst), "l"(gsrc));
}
static __device__ __forceinline__ void ldsm4a(unsigned addr, unsigned* r) {
    asm volatile("ldmatrix.sync.aligned.m8n8.x4.shared.b16 {%0,%1,%2,%3}, [%4];"
                 : "=r"(r[0]), "=r"(r[1]), "=r"(r[2]), "=r"(r[3]) : "r"(addr));
}
#define MMA16816(C, A, b0, b1) \
    asm volatile("mma.sync.aligned.m16n8k16.row.col.f32.f16.f16.f32 " \
        "{%0,%1,%2,%3}, {%4,%5,%6,%7}, {%8,%9}, {%0,%1,%2,%3};" \
        : "+f"((C)[0]), "+f"((C)[1]), "+f"((C)[2]), "+f"((C)[3]) \
        : "r"((A)[0]), "r"((A)[1]), "r"((A)[2]), "r"((A)[3]), "r"(b0), "r"(b1))

static __device__ __forceinline__ float lds_f(unsigned a) {
    float v;
    asm("ld.shared.f32 %0, [%1];" : "=f"(v) : "r"(a));
    return v;
}
static __device__ __forceinline__ unsigned packh2(float hi, float lo) {
    unsigned p;
    asm("cvt.rn.f16x2.f32 %0, %1, %2;" : "=r"(p) : "f"(hi), "f"(lo));
    return p;
}
static __device__ __forceinline__ int tri_start(int i) { return i * (67 - i) / 2; }

// build 2 kp columns (4 k values) of one A buffer pair
static __device__ __forceinline__ void build_pair(
    unsigned An0, unsigned An1, const unsigned* ijo_k0, unsigned zb,
    unsigned rb64, unsigned xorw, int kp) {
    uint2 o01 = *(const uint2*)(ijo_k0 + kp * 2);
    uint2 o23 = *(const uint2*)(ijo_k0 + kp * 2 + 2);
    float w0 = lds_f(zb + (o01.x & 0xFFFFu)) * lds_f(zb + (o01.x >> 16));
    float w1 = lds_f(zb + (o01.y & 0xFFFFu)) * lds_f(zb + (o01.y >> 16));
    float w2 = lds_f(zb + (o23.x & 0xFFFFu)) * lds_f(zb + (o23.x >> 16));
    float w3 = lds_f(zb + (o23.y & 0xFFFFu)) * lds_f(zb + (o23.y >> 16));
    unsigned ph01 = packh2(w1, w0), ph23 = packh2(w3, w2);
    float2 f01 = __half22float2(*(__half2*)&ph01);
    float2 f23 = __half22float2(*(__half2*)&ph23);
    unsigned pr01 = packh2(w1 - f01.y, w0 - f01.x);
    unsigned pr23 = packh2(w3 - f23.y, w2 - f23.x);
    unsigned aoff = rb64 + (((unsigned)(kp * 4)) ^ xorw);
    asm volatile("st.shared.v2.b32 [%0], {%1, %2};"
                 :: "r"(An0 + aoff), "r"(ph01), "r"(ph23));
    asm volatile("st.shared.v2.b32 [%0], {%1, %2};"
                 :: "r"(An1 + aoff), "r"(pr01), "r"(pr23));
}

// ---------------- prep ----------------
__global__ void prep_kernel(const float* __restrict__ mu,
                            const float* __restrict__ S,
                            const int* __restrict__ lab) {
    const int c = blockIdx.x;
    const int t = threadIdx.x;   // 128
    __shared__ float mus[Dn], Sm[Dn], t3s;

    if (t < Dn) mus[t] = mu[c * Dn + t];
    __syncthreads();
    if (t < Dn) {
        float s = 0.f;
#pragma unroll
        for (int e = 0; e < Dn; e++) s += S[(c * Dn + t) * Dn + e] * mus[e];
        Sm[t] = s;
    }
    __syncthreads();
    if (t == 0) {
        float s = 0.f;
        for (int d = 0; d < Dn; d++) s += mus[d] * Sm[d];
        t3s = s;
        int cl = 0;
        for (int k = 0; k < Kn; k++) if (lab[c * Kn + k] != 0) cl = k;
        g_cls[c] = cl;
    }
    __syncthreads();

    for (int k = t; k < KPAD; k += 128) {
        float v; int ii, jj;
        if (k > 560) { v = 0.f; ii = 33; jj = 33; }
        else {
            int i = (int)((67.0f - sqrtf(4489.0f - 8.0f * (float)k)) * 0.5f);
            if (i > 32) i = 32;
            while (i > 0 && tri_start(i) > k) i--;
            while (tri_start(i + 1) <= k) i++;
            int j = i + (k - tri_start(i));
            ii = i; jj = j;
            if (j < Dn)      v = ((i == j) ? 1.f : 2.f) * S[(c * Dn + i) * Dn + j];
            else if (i < Dn) v = -2.f * Sm[i];
            else             v = t3s;
        }
        if (c == 0) g_ijoff[k] = (unsigned)(4 * ii) | ((unsigned)(4 * jj) << 16);

        __half h0 = __float2half_rn(v);
        float r = v - __half2float(h0);
        __half h1 = __float2half_rn(r);

        int ch = k >> 5, kk = k & 31;
        int sw = SWZ64(c * 64 + kk * 2);
        *(__half*)&g_Uh[0][ch][sw] = h0;
        *(__half*)&g_Uh[1][ch][sw] = h1;
    }
}

// ---------------- smem layout (bytes) ----------------
#define OFF_Z     0         // 128*37*4 = 18944
#define OFF_IJO   18944     // 2304 -> 21248
#define OFF_CLS   21248     // 512 -> 21760
#define OFF_LAB   21760     // 5120 -> 26880
#define OFF_CLIST 26880     // 512 -> 27392
#define OFF_PMAX  27392     // 1024 -> 28416
#define OFF_CNT   28416     // 40
#define OFF_COFF  28456     // 40 -> 28496
#define OFF_T     28672     // A triple 49152 + B double 32768; gamma reuse
#define SMEM_SZ   110592

// ---------------- main kernel: 2 blocks/SM ----------------
__global__ void __launch_bounds__(THREADS, 2)
main_kernel(const float* __restrict__ data, float* __restrict__ out) {
    extern __shared__ char sm_[];
    int*    cls_s  = (int*)(sm_ + OFF_CLS);
    float*  lab_s  = (float*)(sm_ + OFF_LAB);
    int*    clist_s= (int*)(sm_ + OFF_CLIST);
    unsigned long long* pmax_s = (unsigned long long*)(sm_ + OFF_PMAX);
    int*    cnt_s  = (int*)(sm_ + OFF_CNT);
    int*    coff_s = (int*)(sm_ + OFF_COFF);
    float*  z_s    = (float*)(sm_ + OFF_Z);
    unsigned* ijo_s= (unsigned*)(sm_ + OFF_IJO);
    float*  gsm    = (float*)(sm_ + OFF_T);   // [128][GST] post-MMA

    const int tid = threadIdx.x;
    const int wid = tid >> 5;
    const int lane = tid & 31;
    const int mw = wid >> 1;          // rows mw*32
    const int nw = wid & 1;           // cols nw*64
    const int bbase = blockIdx.x * ROWS;
    const unsigned sbase = smem_u32(sm_);

    const unsigned tAb = sbase + OFF_T;            // 3 buffers x 16384 (2 splits)
    const unsigned tBb = tAb + 3 * 16384;          // 2 buffers x 16384

    // builder identity
    const int row_b = tid & 127;
    const int kp0_b = (tid >> 7) * 8;
    const unsigned zb = sbase + OFF_Z + (unsigned)row_b * 148;
    const unsigned rb64 = (unsigned)row_b * 64;
    const unsigned xorw = (rb64 >> 3) & 0x30;

    // hoisted swizzled LDSM fragment offsets
    unsigned offA[4], offB[8];
#pragma unroll
    for (int mf = 0; mf < 2; mf++)
#pragma unroll
        for (int ks = 0; ks < 2; ks++) {
            unsigned o = (unsigned)((mw * 32 + mf * 16 + (lane & 15)) * 64 +
                                    ks * 32 + ((lane >> 4) << 4));
            offA[mf * 2 + ks] = SWZ64(o);
        }
#pragma unroll
    for (int nf2 = 0; nf2 < 4; nf2++)
#pragma unroll
        for (int ks = 0; ks < 2; ks++) {
            unsigned o = (unsigned)((nw * 64 + nf2 * 16 + (lane & 15)) * 64 +
                                    ks * 32 + ((lane >> 4) << 4));
            offB[nf2 * 2 + ks] = SWZ64(o);
        }

    // prologue
    if (tid < Cn) cls_s[tid] = g_cls[tid];
    if (tid < ROWS) pmax_s[tid] = 0ull;
    if (tid < Kn) cnt_s[tid] = 0;
    for (int i = tid; i < KPAD; i += THREADS) ijo_s[i] = g_ijoff[i];
    for (int idx = tid; idx < ROWS * Dn; idx += THREADS) {
        int row = idx >> 5, d = idx & 31;
        z_s[row * 37 + d] = data[(size_t)(bbase + row) * Dn + d];
    }
    if (tid < ROWS) { z_s[tid * 37 + 32] = 1.f; z_s[tid * 37 + 33] = 0.f; }

    // prefetch B chunk 0 into B buf 0
#pragma unroll
    for (int s = 0; s < 2; s++)
        for (int e = tid; e < TILE / 16; e += THREADS)
            cp16(tBb + s * TILE + e * 16, &g_Uh[s][0][e * 16]);
    asm volatile("cp.async.commit_group;");
    __syncthreads();   // z, cls, cnt-zero visible

    if (tid < Cn) atomicAdd(&cnt_s[cls_s[tid]], 1);

    // pre-build A chunks 0 and 1 (distance-2 pipeline prologue)
#pragma unroll
    for (int st = 0; st < 2; st++) {
        unsigned An0 = tAb + st * 16384, An1 = An0 + TILE;
        const unsigned* ij0 = ijo_s + st * KC;
#pragma unroll
        for (int pp = 0; pp < 4; pp++)
            build_pair(An0, An1, ij0, zb, rb64, xorw, kp0_b + pp * 2);
    }

    float acc[16][4];
#pragma unroll
    for (int i = 0; i < 16; i++)
#pragma unroll
        for (int q = 0; q < 4; q++) acc[i][q] = 0.f;

    for (int ch = 0; ch < NCH; ch++) {
        asm volatile("cp.async.wait_group 0;");   // B[ch] landed
        __syncthreads();   // A[ch] built (prologue / ch-2); prev reads done

        // CSR build hidden under chunk-0 MMA
        if (ch == 0 && tid < Kn) {
            int off = 0;
            for (int j = 0; j < tid; j++) off += cnt_s[j];
            coff_s[tid] = off;
            for (int c = 0; c < Cn; c++)
                if (cls_s[c] == tid) clist_s[off++] = c;
        }

        if (ch + 1 < NCH) {
            unsigned dst = tBb + ((ch + 1) & 1) * 16384;
#pragma unroll
            for (int s = 0; s < 2; s++)
                for (int e = tid; e < TILE / 16; e += THREADS)
                    cp16(dst + s * TILE + e * 16, &g_Uh[s][ch + 1][e * 16]);
            asm volatile("cp.async.commit_group;");
        }

        const unsigned A0 = tAb + (ch % 3) * 16384, A1 = A0 + TILE;
        const unsigned B0 = tBb + (ch & 1) * 16384, B1 = B0 + TILE;
        const unsigned An0 = tAb + ((ch + 2) % 3) * 16384, An1 = An0 + TILE;
        const unsigned* ijn = ijo_s + (ch + 2) * KC;
        const bool do_build = (ch + 2 < NCH);

#pragma unroll
        for (int ks = 0; ks < 2; ks++) {
            unsigned a0[2][4], a1[2][4];
#pragma unroll
            for (int mf = 0; mf < 2; mf++) {
                ldsm4a(A0 + offA[mf * 2 + ks], a0[mf]);
                ldsm4a(A1 + offA[mf * 2 + ks], a1[mf]);
            }
            // software-pipelined B fragments: prefetch next nf2 while MMAing
            unsigned bb0[2][4], bb1[2][4];
            ldsm4a(B0 + offB[ks], bb0[0]);
            ldsm4a(B1 + offB[ks], bb1[0]);
#pragma unroll
            for (int nf2 = 0; nf2 < 4; nf2++) {
                const int cur = nf2 & 1;
                if (nf2 < 3) {
                    ldsm4a(B0 + offB[(nf2 + 1) * 2 + ks], bb0[1 - cur]);
                    ldsm4a(B1 + offB[(nf2 + 1) * 2 + ks], bb1[1 - cur]);
                }
#pragma unroll
                for (int mf = 0; mf < 2; mf++)
#pragma unroll
                    for (int h = 0; h < 2; h++) {
                        float* C = acc[mf * 8 + nf2 * 2 + h];
                        MMA16816(C, a0[mf], bb0[cur][h], bb0[cur][h + 2]);
                        MMA16816(C, a0[mf], bb1[cur][h], bb1[cur][h + 2]);
                        MMA16816(C, a1[mf], bb0[cur][h], bb0[cur][h + 2]);
                    }
                // spread the distance-2 A build across nf2 iterations
                if (do_build && (nf2 & 1))
                    build_pair(An0, An1, ijn, zb, rb64, xorw,
                               kp0_b + ks * 4 + (nf2 >> 1) * 2);
            }
        }
    }
    __syncthreads();   // MMA done; tile smem -> gamma staging

    // ---------------- phase 1: exp + stage gamma + argmax ----------------
    const int lr = lane >> 2, lc = (lane & 3) * 2;
#pragma unroll
    for (int mf = 0; mf < 2; mf++) {
        unsigned long long rmax[2] = {0ull, 0ull};
        const int row0 = mw * 32 + mf * 16 + lr;
#pragma unroll
        for (int nf2 = 0; nf2 < 4; nf2++)
#pragma unroll
            for (int h = 0; h < 2; h++) {
                float* C = acc[mf * 8 + nf2 * 2 + h];
                int col = nw * 64 + nf2 * 16 + h * 8 + lc;
                float g0 = __expf(-0.5f * C[0]);
                float g1 = __expf(-0.5f * C[1]);
                float g2 = __expf(-0.5f * C[2]);
                float g3 = __expf(-0.5f * C[3]);
                *(float2*)&gsm[row0 * GST + col]       = make_float2(g0, g1);
                *(float2*)&gsm[(row0 + 8) * GST + col] = make_float2(g2, g3);
                unsigned long long p0 =
                    ((unsigned long long)__float_as_uint(g0) << 32) | (unsigned)(127 - col);
                unsigned long long p1 =
                    ((unsigned long long)__float_as_uint(g1) << 32) | (unsigned)(126 - col);
                unsigned long long p2 =
                    ((unsigned long long)__float_as_uint(g2) << 32) | (unsigned)(127 - col);
                unsigned long long p3 =
                    ((unsigned long long)__float_as_uint(g3) << 32) | (unsigned)(126 - col);
                if (p0 > rmax[0]) rmax[0] = p0;
                if (p1 > rmax[0]) rmax[0] = p1;
                if (p2 > rmax[1]) rmax[1] = p2;
                if (p3 > rmax[1]) rmax[1] = p3;
            }
#pragma unroll
        for (int m = 1; m <= 2; m <<= 1) {
#pragma unroll
            for (int rr = 0; rr < 2; rr++) {
                unsigned long long o = __shfl_xor_sync(0xffffffffu, rmax[rr], m);
                if (o > rmax[rr]) rmax[rr] = o;
            }
        }
        if ((lane & 3) == 0) {
            atomicMax(&pmax_s[row0], rmax[0]);
            atomicMax(&pmax_s[row0 + 8], rmax[1]);
        }
    }
    __syncthreads();

    // ---------------- phase 2: class-binned sums (no atomics) ----------------
#pragma unroll
    for (int it = 0; it < 5; it++) {
        int u = it * THREADS + tid;        // 1280 units: k = u>>7, row = u&127
        int k = u >> 7, row = u & 127;
        int off = coff_s[k], n = cnt_s[k];
        float s = 0.f;
        for (int p = 0; p < n; p++) s += gsm[row * GST + clist_s[off + p]];
        lab_s[k * ROWS + row] = s;
    }
    __syncthreads();

    // ---------------- final: normalize + outputs ----------------
    if (tid < ROWS) {
        const int row = tid;
        const size_t b = (size_t)bbase + row;
        float bins[Kn];
        float S = 0.f;
#pragma unroll
        for (int k = 0; k < Kn; k++) { bins[k] = lab_s[k * ROWS + row]; S += bins[k]; }
        float inv = 1.f / (S + 1e-12f);
        float best = -1.f;
        int kb = 0;
#pragma unroll
        for (int k = 0; k < Kn; k++) {
            float ls = bins[k] * inv;
            out[b * Kn + k] = ls;
            if (ls > best) { best = ls; kb = k; }
        }
        out[(size_t)Bn * Kn + b] = (float)kb;
        out[(size_t)Bn * Kn + Bn + b] = (float)(127 - (int)(pmax_s[row] & 0xFFu));
    }
}

extern "C" void kernel_launch(void* const* d_in, const int* in_sizes, int n_in,
                              void* d_out, int out_size) {
    const float* data = (const float*)d_in[0];
    const float* mu   = (const float*)d_in[1];
    const float* Sinv = (const float*)d_in[2];
    const int*   lab  = (const int*)d_in[3];
    float* out = (float*)d_out;

    static int smem_set = 0;
    if (!smem_set) {
        cudaFuncSetAttribute(main_kernel,
                             cudaFuncAttributeMaxDynamicSharedMemorySize, SMEM_SZ);
        smem_set = 1;
    }
    prep_kernel<<<Cn, 128>>>(mu, Sinv, lab);
    main_kernel<<<Bn / ROWS, THREADS, SMEM_SZ>>>(data, out);
}